// round 13
// baseline (speedup 1.0000x reference)
#include <cuda_runtime.h>
#include <cuda_fp16.h>
#include <cstdint>
#include <cstddef>

typedef unsigned long long ull;

#define B_   8
#define EH_  768
#define T_   512
#define PH_  320
#define U_   128
#define JH_  320
#define C_   34
#define NPAD 40
#define NT5  5

// ---------------- scratch: e/p activations stored as half2 words ----------
__device__ __align__(16) uint32_t g_e[B_ * T_ * JH_ / 2];
__device__ __align__(16) uint32_t g_p[B_ * U_ * JH_ / 2];

// ---------------- helpers ----------------
__device__ __forceinline__ uint32_t pkh(float lo, float hi) {
    uint32_t d;
    asm("cvt.rn.f16x2.f32 %0, %1, %2;" : "=r"(d) : "f"(hi), "f"(lo));
    return d;
}
__device__ __forceinline__ uint32_t hadd2u(uint32_t a, uint32_t b) {
    uint32_t d;
    asm("add.f16x2 %0, %1, %2;" : "=r"(d) : "r"(a), "r"(b));
    return d;
}
__device__ __forceinline__ uint32_t hrelu2(uint32_t a) {
    uint32_t d;
    asm("max.f16x2 %0, %1, %2;" : "=r"(d) : "r"(a), "r"(0u));
    return d;
}
__device__ __forceinline__ void mma_f16(float* d, const uint32_t* a,
                                        uint32_t b0, uint32_t b1) {
    asm volatile(
        "mma.sync.aligned.m16n8k16.row.col.f32.f16.f16.f32 "
        "{%0,%1,%2,%3}, {%4,%5,%6,%7}, {%8,%9}, {%0,%1,%2,%3};"
        : "+f"(d[0]), "+f"(d[1]), "+f"(d[2]), "+f"(d[3])
        : "r"(a[0]), "r"(a[1]), "r"(a[2]), "r"(a[3]), "r"(b0), "r"(b1));
}

// =====================================================================
// proj_kernel: fp16 m16n8k16 MMA computing D^T = W @ X (half the MMA
// count of the tf32 k8 version at the same legacy-HMMA issue ceiling).
//   A = fp16(W) [j][h2-pairs], B = fp16(X) [h2-pairs][l].
//   Block: 64 j x 64 l, 128 thr (4 warps), warp = 2 m16 x 4 n8.
//   Output packed half2 into g_e / g_p via SMEM staging.
// =====================================================================
#define PWS 20        // sW j-stride in words (16 h2 + 4 pad -> conflict-free)
#define PXS 68        // sX h2-row stride in words (64 l + 4 pad)
#define SS_STRW 36    // staging row stride in words (72 halves)

__global__ void __launch_bounds__(128, 6) proj_kernel(
    const float* __restrict__ enc, const float* __restrict__ W_enc,
    const float* __restrict__ b_enc, const float* __restrict__ dec,
    const float* __restrict__ W_pred, const float* __restrict__ b_pred)
{
    __shared__ __align__(16) uint32_t sW[64 * PWS];    // 5120 B
    __shared__ __align__(16) uint32_t sXS[64 * SS_STRW]; // 9216 B (X tile / staging)

    const int blk = blockIdx.x;
    const float *X, *W, *bias;
    uint32_t* outw;
    int H, L, b, j0, l0;
    if (blk < 320) {
        b = blk / 40; int r = blk - b * 40;
        j0 = (r >> 3) * 64; l0 = (r & 7) * 64;
        X = enc; W = W_enc; bias = b_enc; outw = g_e; H = EH_; L = T_;
    } else {
        int bi = blk - 320; b = bi / 10; int r = bi - b * 10;
        j0 = (r >> 1) * 64; l0 = (r & 1) * 64;
        X = dec; W = W_pred; bias = b_pred; outw = g_p; H = PH_; L = U_;
    }
    const float* Xb = X + (size_t)b * H * L + l0;
    const float* Wb = W + (size_t)j0 * H;

    const int tid  = threadIdx.x;
    const int wid  = tid >> 5;
    const int lane = tid & 31;
    const int c    = lane & 3;
    const int rn   = lane >> 2;
    const int mpair = wid >> 1;
    const int nhalf = wid & 1;

    float acc[2][4][4];
    #pragma unroll
    for (int mt = 0; mt < 2; mt++)
        #pragma unroll
        for (int nt = 0; nt < 4; nt++)
            #pragma unroll
            for (int i = 0; i < 4; i++) acc[mt][nt][i] = 0.f;

    const int nk = H >> 5;
    for (int kc = 0; kc < nk; kc++) {
        const int k0 = kc * 32;
        // X tile: pack pairs of h-rows into half2 [h2][l]  (16 x 64 words)
        #pragma unroll
        for (int i = 0; i < 2; i++) {
            int idx = tid + i * 128;
            int h2 = idx >> 4, l4 = (idx & 15) * 4;
            const float* r0 = Xb + (size_t)(k0 + 2 * h2) * L + l4;
            float4 v0 = *(const float4*)r0;
            float4 v1 = *(const float4*)(r0 + L);
            uint4 u;
            u.x = pkh(v0.x, v1.x);
            u.y = pkh(v0.y, v1.y);
            u.z = pkh(v0.z, v1.z);
            u.w = pkh(v0.w, v1.w);
            *(uint4*)(sXS + h2 * PXS + l4) = u;
        }
        // W tile: [j][h2] half2, native row-major reads
        #pragma unroll
        for (int i = 0; i < 4; i++) {
            int idx = tid + i * 128;
            int jj = idx >> 3, h4 = (idx & 7) * 4;
            float4 v = *(const float4*)(Wb + (size_t)jj * H + k0 + h4);
            uint2 u;
            u.x = pkh(v.x, v.y);
            u.y = pkh(v.z, v.w);
            *(uint2*)(sW + jj * PWS + (h4 >> 1)) = u;
        }
        __syncthreads();
        #pragma unroll
        for (int s = 0; s < 2; s++) {
            const int hb = 8 * s;
            uint32_t a0[4], a1[4];
            const uint32_t* w0p = sW + (32 * mpair + rn) * PWS + hb + c;
            a0[0] = w0p[0];
            a0[1] = w0p[8 * PWS];
            a0[2] = w0p[4];
            a0[3] = w0p[8 * PWS + 4];
            const uint32_t* w1p = w0p + 16 * PWS;
            a1[0] = w1p[0];
            a1[1] = w1p[8 * PWS];
            a1[2] = w1p[4];
            a1[3] = w1p[8 * PWS + 4];
            const uint32_t* bp = sXS + (hb + c) * PXS + 32 * nhalf + rn;
            #pragma unroll
            for (int nt = 0; nt < 4; nt++) {
                uint32_t b0 = bp[8 * nt];
                uint32_t b1 = bp[4 * PXS + 8 * nt];
                mma_f16(acc[0][nt], a0, b0, b1);
                mma_f16(acc[1][nt], a1, b0, b1);
            }
        }
        __syncthreads();
    }

    // ---- epilogue: +bias, stage as half [l][j], flush packed half2 ----
    float bj[2][2];
    #pragma unroll
    for (int mt = 0; mt < 2; mt++) {
        int jr = j0 + 16 * (2 * mpair + mt) + rn;
        bj[mt][0] = bias[jr];
        bj[mt][1] = bias[jr + 8];
    }
    __half* sS = (__half*)sXS;   // [64 l][72 halves]
    #pragma unroll
    for (int mt = 0; mt < 2; mt++) {
        int jloc = 16 * (2 * mpair + mt) + rn;
        #pragma unroll
        for (int nt = 0; nt < 4; nt++) {
            int lloc = 8 * (4 * nhalf + nt) + 2 * c;
            sS[lloc * 72 + jloc]           = __float2half(acc[mt][nt][0] + bj[mt][0]);
            sS[(lloc + 1) * 72 + jloc]     = __float2half(acc[mt][nt][1] + bj[mt][0]);
            sS[lloc * 72 + jloc + 8]       = __float2half(acc[mt][nt][2] + bj[mt][1]);
            sS[(lloc + 1) * 72 + jloc + 8] = __float2half(acc[mt][nt][3] + bj[mt][1]);
        }
    }
    __syncthreads();
    #pragma unroll
    for (int i = 0; i < 4; i++) {
        int idx = tid + i * 128;
        int l = idx >> 3, q = idx & 7;
        uint4 v = *(const uint4*)(sXS + l * SS_STRW + q * 4);
        *(uint4*)(outw + ((size_t)b * L + l0 + l) * 160 + (j0 >> 1) + q * 4) = v;
    }
}

// =====================================================================
// joint_mma_kernel (unchanged from R9): fp16 mma.sync, low-footprint
// warps, 8 passes of 8 t-rows x 16 u, pair-interleaved SMEM (LDS.64).
// =====================================================================
#define EPS   168
#define WG44  44
#define OFF_W 0
#define W_WORDS (20 * 4 * WG44 * 2)     // 7040
#define OFF_E (OFF_W + W_WORDS)         // 7040
#define E_WORDS (8 * EPS)               // 1344
#define OFF_P (OFF_E + E_WORDS)         // 8384
#define P_WORDS (16 * EPS)              // 2688
#define OFF_B (OFF_P + P_WORDS)         // 11072
#define SMEM_JT ((OFF_B + NPAD) * 4)    // 44448 B

__global__ void __launch_bounds__(128, 5) joint_mma_kernel(
    const float* __restrict__ W_out, const float* __restrict__ b_out,
    float* __restrict__ out)
{
    extern __shared__ __align__(16) uint32_t sm[];
    float* sB = (float*)(sm + OFF_B);

    const int tid  = threadIdx.x;
    const int wid  = tid >> 5;
    const int lane = tid & 31;
    const int c    = lane & 3;
    const int rn   = lane >> 2;
    const int c2   = c * 2;
    const int b    = blockIdx.y;
    const int u0   = blockIdx.x * 16;
    const int tbase = blockIdx.z * 64;

    // ---- W_out -> [g][c][n][pair] half2 layout (div-free) ----
    for (int n = wid; n < NPAD; n += 4) {
        const float2* wrow = (const float2*)(W_out + (size_t)n * JH_);
        #pragma unroll
        for (int k2s = 0; k2s < 160; k2s += 32) {
            int k2 = k2s + lane;
            uint32_t v = 0u;
            if (n < C_) { float2 w = wrow[k2]; v = pkh(w.x, w.y); }
            int g = k2 >> 3, r = k2 & 7;
            sm[OFF_W + ((g * 4 + (r & 3)) * WG44 + n) * 2 + (r >> 2)] = v;
        }
    }
    if (tid < NPAD) sB[tid] = (tid < C_) ? b_out[tid] : -1e30f;

    // ---- p tile (16 u rows), pair-interleaved ----
    {
        const uint4* src = (const uint4*)(g_p + ((size_t)b * U_ + u0) * 160);
        #pragma unroll
        for (int i = 0; i < 5; i++) {
            int idx = tid + i * 128;
            int row = idx / 40, q = idx - row * 40;
            uint4 v = src[idx];
            uint32_t* d = sm + OFF_P + row * EPS + (q >> 1) * 8 + (q & 1);
            d[0] = v.x; d[2] = v.y; d[4] = v.z; d[6] = v.w;
        }
    }

    // e fill geometry: 8 rows x 40 uint4 = 320 items, 128 threads
    int frow[3], fq[3];
    bool fon[3];
    #pragma unroll
    for (int i = 0; i < 3; i++) {
        int idx = tid + i * 128;
        fon[i] = idx < 320;
        int idc = fon[i] ? idx : 0;
        frow[i] = idc / 40; fq[i] = idc - frow[i] * 40;
    }

    const uint32_t* eB  = sm + OFF_E + (2 * wid) * EPS + c2;
    const uint32_t* pB0 = sm + OFF_P + rn * EPS + c2;
    const uint32_t* pB1 = pB0 + 8 * EPS;
    const uint32_t* wB  = sm + OFF_W + (c * WG44 + rn) * 2;

    float bn[NT5][2];
    #pragma unroll
    for (int nt = 0; nt < NT5; nt++) {
        bn[nt][0] = (nt * 8 + c2 < C_)     ? b_out[nt * 8 + c2]     : -1e30f;
        bn[nt][1] = (nt * 8 + c2 + 1 < C_) ? b_out[nt * 8 + c2 + 1] : -1e30f;
    }

    for (int pass = 0; pass < 8; pass++) {
        const int t0 = tbase + pass * 8;
        __syncthreads();
        {
            const uint4* src = (const uint4*)(g_e + ((size_t)b * T_ + t0) * 160);
            #pragma unroll
            for (int i = 0; i < 3; i++) {
                if (fon[i]) {
                    uint4 v = src[tid + i * 128];
                    uint32_t* d = sm + OFF_E + frow[i] * EPS
                                + (fq[i] >> 1) * 8 + (fq[i] & 1);
                    d[0] = v.x; d[2] = v.y; d[4] = v.z; d[6] = v.w;
                }
            }
        }
        __syncthreads();

        float acc[2][NT5][4];
        #pragma unroll
        for (int mt = 0; mt < 2; mt++)
            #pragma unroll
            for (int nt = 0; nt < NT5; nt++)
                #pragma unroll
                for (int i = 0; i < 4; i++) acc[mt][nt][i] = 0.f;

        #pragma unroll 4
        for (int g = 0; g < 20; g++) {
            uint2 pv0 = *(const uint2*)(pB0 + 8 * g);
            uint2 pv1 = *(const uint2*)(pB1 + 8 * g);
            uint32_t A[2][4];
            #pragma unroll
            for (int mt = 0; mt < 2; mt++) {
                uint2 ev = *(const uint2*)(eB + mt * EPS + 8 * g);
                A[mt][0] = hrelu2(hadd2u(ev.x, pv0.x));
                A[mt][1] = hrelu2(hadd2u(ev.x, pv1.x));
                A[mt][2] = hrelu2(hadd2u(ev.y, pv0.y));
                A[mt][3] = hrelu2(hadd2u(ev.y, pv1.y));
            }
            #pragma unroll
            for (int nt = 0; nt < NT5; nt++) {
                uint2 wv = *(const uint2*)(wB + g * (4 * WG44 * 2) + nt * 16);
                mma_f16(acc[0][nt], A[0], wv.x, wv.y);
                mma_f16(acc[1][nt], A[1], wv.x, wv.y);
            }
        }

        #pragma unroll
        for (int mt = 0; mt < 2; mt++) {
            const int t = t0 + 2 * wid + mt;
            #pragma unroll
            for (int hf = 0; hf < 2; hf++) {
                float v[NT5][2];
                #pragma unroll
                for (int nt = 0; nt < NT5; nt++) {
                    v[nt][0] = acc[mt][nt][hf * 2 + 0] + bn[nt][0];
                    v[nt][1] = acc[mt][nt][hf * 2 + 1] + bn[nt][1];
                }
                float m = v[0][0];
                #pragma unroll
                for (int nt = 0; nt < NT5; nt++) {
                    m = fmaxf(m, v[nt][0]);
                    m = fmaxf(m, v[nt][1]);
                }
                m = fmaxf(m, __shfl_xor_sync(0xffffffffu, m, 1));
                m = fmaxf(m, __shfl_xor_sync(0xffffffffu, m, 2));
                float s = 0.f;
                #pragma unroll
                for (int nt = 0; nt < NT5; nt++) {
                    s += __expf(v[nt][0] - m);
                    s += __expf(v[nt][1] - m);
                }
                s += __shfl_xor_sync(0xffffffffu, s, 1);
                s += __shfl_xor_sync(0xffffffffu, s, 2);
                float lse = m + __logf(s);

                const int u = u0 + rn + 8 * hf;
                float* o = out + (((size_t)b * T_ + t) * U_ + u) * C_;
                #pragma unroll
                for (int nt = 0; nt < 4; nt++)
                    *(float2*)(o + nt * 8 + c2) =
                        make_float2(v[nt][0] - lse, v[nt][1] - lse);
                if (c == 0)
                    *(float2*)(o + 32) = make_float2(v[4][0] - lse, v[4][1] - lse);
            }
        }
    }
}

// =====================================================================
// kernel_launch
// Inputs: enc, dec, W_enc, b_enc, W_pred, b_pred, W_out, b_out
// =====================================================================
extern "C" void kernel_launch(void* const* d_in, const int* in_sizes, int n_in,
                              void* d_out, int out_size)
{
    const float* enc    = (const float*)d_in[0];
    const float* dec    = (const float*)d_in[1];
    const float* W_enc  = (const float*)d_in[2];
    const float* b_enc  = (const float*)d_in[3];
    const float* W_pred = (const float*)d_in[4];
    const float* b_pred = (const float*)d_in[5];
    const float* W_out  = (const float*)d_in[6];
    const float* b_outp = (const float*)d_in[7];
    float* out = (float*)d_out;

    (void)cudaFuncSetAttribute(joint_mma_kernel,
                               cudaFuncAttributeMaxDynamicSharedMemorySize,
                               SMEM_JT);

    // proj: 320 enc + 80 dec blocks, single wave, fp16 MMA
    proj_kernel<<<400, 128>>>(enc, W_enc, b_enc, dec, W_pred, b_pred);

    // joint: 512 blocks, single resident wave
    joint_mma_kernel<<<dim3(U_ / 16, B_, T_ / 64), 128, SMEM_JT>>>(
        W_out, b_outp, out);
}

// round 15
// speedup vs baseline: 1.2249x; 1.2249x over previous
#include <cuda_runtime.h>
#include <cuda_fp16.h>
#include <cstdint>
#include <cstddef>

typedef unsigned long long ull;

#define B_   8
#define EH_  768
#define T_   512
#define PH_  320
#define U_   128
#define JH_  320
#define C_   34
#define NPAD 40
#define NT5  5

// ---------------- scratch: e/p activations stored as half2 words ----------
__device__ __align__(16) uint32_t g_e[B_ * T_ * JH_ / 2];
__device__ __align__(16) uint32_t g_p[B_ * U_ * JH_ / 2];

// ---------------- helpers ----------------
__device__ __forceinline__ uint32_t pkh(float lo, float hi) {
    uint32_t d;
    asm("cvt.rn.f16x2.f32 %0, %1, %2;" : "=r"(d) : "f"(hi), "f"(lo));
    return d;
}
__device__ __forceinline__ uint32_t hadd2u(uint32_t a, uint32_t b) {
    uint32_t d;
    asm("add.f16x2 %0, %1, %2;" : "=r"(d) : "r"(a), "r"(b));
    return d;
}
__device__ __forceinline__ uint32_t hrelu2(uint32_t a) {
    uint32_t d;
    asm("max.f16x2 %0, %1, %2;" : "=r"(d) : "r"(a), "r"(0u));
    return d;
}
__device__ __forceinline__ void mma_f16(float* d, const uint32_t* a,
                                        uint32_t b0, uint32_t b1) {
    asm volatile(
        "mma.sync.aligned.m16n8k16.row.col.f32.f16.f16.f32 "
        "{%0,%1,%2,%3}, {%4,%5,%6,%7}, {%8,%9}, {%0,%1,%2,%3};"
        : "+f"(d[0]), "+f"(d[1]), "+f"(d[2]), "+f"(d[3])
        : "r"(a[0]), "r"(a[1]), "r"(a[2]), "r"(a[3]), "r"(b0), "r"(b1));
}

// =====================================================================
// proj_kernel: fp16 m16n8k16 MMA, D^T = W @ X, SMALL TILES for supply.
//   Block: 64 j x 32 l, 128 thr (4 warps), warp = 2 m16(j) x 2 n8(l).
//   Grid: enc 640 + dec 160 = 800 blocks (~5.4 resident blocks/SM).
//   X tile stride 40 words: 8c+rn hits all 32 banks (conflict-free).
// =====================================================================
#define PWS 20        // sW j-stride (words): conflict-free A-frag loads
#define PXS 40        // sX h2-row stride (words): conflict-free B-frag loads
#define SS_STRW 36    // staging row stride (words) = 72 halves

__global__ void __launch_bounds__(128, 6) proj_kernel(
    const float* __restrict__ enc, const float* __restrict__ W_enc,
    const float* __restrict__ b_enc, const float* __restrict__ dec,
    const float* __restrict__ W_pred, const float* __restrict__ b_pred)
{
    __shared__ __align__(16) uint32_t sW[64 * PWS];      // 5120 B
    __shared__ __align__(16) uint32_t sXS[32 * SS_STRW]; // 4608 B (X / staging)

    const int blk = blockIdx.x;
    const float *X, *W, *bias;
    uint32_t* outw;
    int H, L, b, j0, l0;
    if (blk < 640) {            // enc: 8b x 5j x 16l
        b = blk / 80; int r = blk - b * 80;
        j0 = (r >> 4) * 64; l0 = (r & 15) * 32;
        X = enc; W = W_enc; bias = b_enc; outw = g_e; H = EH_; L = T_;
    } else {                    // dec: 8b x 5j x 4l
        int bi = blk - 640; b = bi / 20; int r = bi - b * 20;
        j0 = (r >> 2) * 64; l0 = (r & 3) * 32;
        X = dec; W = W_pred; bias = b_pred; outw = g_p; H = PH_; L = U_;
    }
    const float* Xb = X + (size_t)b * H * L + l0;
    const float* Wb = W + (size_t)j0 * H;

    const int tid  = threadIdx.x;
    const int wid  = tid >> 5;
    const int lane = tid & 31;
    const int c    = lane & 3;
    const int rn   = lane >> 2;
    const int mpair = wid >> 1;   // m16 tiles {2mp, 2mp+1}
    const int nhalf = wid & 1;    // n8 tiles {2nh, 2nh+1}

    float acc[2][2][4];
    #pragma unroll
    for (int mt = 0; mt < 2; mt++)
        #pragma unroll
        for (int nt = 0; nt < 2; nt++)
            #pragma unroll
            for (int i = 0; i < 4; i++) acc[mt][nt][i] = 0.f;

    const int nk = H >> 5;
    for (int kc = 0; kc < nk; kc++) {
        const int k0 = kc * 32;
        // X tile: pack h-row pairs into half2 [h2][l], 16 x 32 words
        {
            int h2 = tid >> 3, l4 = (tid & 7) * 4;
            const float* r0 = Xb + (size_t)(k0 + 2 * h2) * L + l4;
            float4 v0 = *(const float4*)r0;
            float4 v1 = *(const float4*)(r0 + L);
            uint4 u;
            u.x = pkh(v0.x, v1.x);
            u.y = pkh(v0.y, v1.y);
            u.z = pkh(v0.z, v1.z);
            u.w = pkh(v0.w, v1.w);
            *(uint4*)(sXS + h2 * PXS + l4) = u;
        }
        // W tile: [j][h2] half2, native row-major reads
        #pragma unroll
        for (int i = 0; i < 4; i++) {
            int idx = tid + i * 128;
            int jj = idx >> 3, h4 = (idx & 7) * 4;
            float4 v = *(const float4*)(Wb + (size_t)jj * H + k0 + h4);
            uint2 u;
            u.x = pkh(v.x, v.y);
            u.y = pkh(v.z, v.w);
            *(uint2*)(sW + jj * PWS + (h4 >> 1)) = u;
        }
        __syncthreads();
        #pragma unroll
        for (int s = 0; s < 2; s++) {
            const int hb = 8 * s;
            uint32_t a0[4], a1[4];
            const uint32_t* w0p = sW + (32 * mpair + rn) * PWS + hb + c;
            a0[0] = w0p[0];
            a0[1] = w0p[8 * PWS];
            a0[2] = w0p[4];
            a0[3] = w0p[8 * PWS + 4];
            const uint32_t* w1p = w0p + 16 * PWS;
            a1[0] = w1p[0];
            a1[1] = w1p[8 * PWS];
            a1[2] = w1p[4];
            a1[3] = w1p[8 * PWS + 4];
            const uint32_t* bp = sXS + (hb + c) * PXS + 16 * nhalf + rn;
            #pragma unroll
            for (int nt = 0; nt < 2; nt++) {
                uint32_t b0 = bp[8 * nt];
                uint32_t b1 = bp[4 * PXS + 8 * nt];
                mma_f16(acc[0][nt], a0, b0, b1);
                mma_f16(acc[1][nt], a1, b0, b1);
            }
        }
        __syncthreads();
    }

    // ---- epilogue: +bias, stage as half [l][j], flush packed half2 ----
    float bj[2][2];
    #pragma unroll
    for (int mt = 0; mt < 2; mt++) {
        int jr = j0 + 16 * (2 * mpair + mt) + rn;
        bj[mt][0] = bias[jr];
        bj[mt][1] = bias[jr + 8];
    }
    __half* sS = (__half*)sXS;   // [32 l][72 halves]
    #pragma unroll
    for (int mt = 0; mt < 2; mt++) {
        int jloc = 16 * (2 * mpair + mt) + rn;
        #pragma unroll
        for (int nt = 0; nt < 2; nt++) {
            int lloc = 8 * (2 * nhalf + nt) + 2 * c;
            sS[lloc * 72 + jloc]           = __float2half(acc[mt][nt][0] + bj[mt][0]);
            sS[(lloc + 1) * 72 + jloc]     = __float2half(acc[mt][nt][1] + bj[mt][0]);
            sS[lloc * 72 + jloc + 8]       = __float2half(acc[mt][nt][2] + bj[mt][1]);
            sS[(lloc + 1) * 72 + jloc + 8] = __float2half(acc[mt][nt][3] + bj[mt][1]);
        }
    }
    __syncthreads();
    // flush: 32 rows x 32 words
    #pragma unroll
    for (int i = 0; i < 2; i++) {
        int idx = tid + i * 128;
        int l = idx >> 3, q = idx & 7;
        uint4 v = *(const uint4*)(sXS + l * SS_STRW + q * 4);
        *(uint4*)(outw + ((size_t)b * L + l0 + l) * 160 + (j0 >> 1) + q * 4) = v;
    }
}

// =====================================================================
// joint_mma_kernel: fp16 mma.sync, 4 passes of 8 t-rows x 16 u.
//   Grid 1024 blocks (T/32 groups) -> wave-1 residency 5 blocks/SM.
//   Inner loop / layouts identical to the validated R9 kernel.
// =====================================================================
#define EPS   168
#define WG44  44
#define OFF_W 0
#define W_WORDS (20 * 4 * WG44 * 2)     // 7040
#define OFF_E (OFF_W + W_WORDS)         // 7040
#define E_WORDS (8 * EPS)               // 1344
#define OFF_P (OFF_E + E_WORDS)         // 8384
#define P_WORDS (16 * EPS)              // 2688
#define OFF_B (OFF_P + P_WORDS)         // 11072
#define SMEM_JT ((OFF_B + NPAD) * 4)    // 44448 B

__global__ void __launch_bounds__(128, 5) joint_mma_kernel(
    const float* __restrict__ W_out, const float* __restrict__ b_out,
    float* __restrict__ out)
{
    extern __shared__ __align__(16) uint32_t sm[];
    float* sB = (float*)(sm + OFF_B);

    const int tid  = threadIdx.x;
    const int wid  = tid >> 5;
    const int lane = tid & 31;
    const int c    = lane & 3;
    const int rn   = lane >> 2;
    const int c2   = c * 2;
    const int b    = blockIdx.y;
    const int u0   = blockIdx.x * 16;
    const int tbase = blockIdx.z * 32;

    // ---- W_out -> [g][c][n][pair] half2 layout (div-free) ----
    for (int n = wid; n < NPAD; n += 4) {
        const float2* wrow = (const float2*)(W_out + (size_t)n * JH_);
        #pragma unroll
        for (int k2s = 0; k2s < 160; k2s += 32) {
            int k2 = k2s + lane;
            uint32_t v = 0u;
            if (n < C_) { float2 w = wrow[k2]; v = pkh(w.x, w.y); }
            int g = k2 >> 3, r = k2 & 7;
            sm[OFF_W + ((g * 4 + (r & 3)) * WG44 + n) * 2 + (r >> 2)] = v;
        }
    }
    if (tid < NPAD) sB[tid] = (tid < C_) ? b_out[tid] : -1e30f;

    // ---- p tile (16 u rows), pair-interleaved ----
    {
        const uint4* src = (const uint4*)(g_p + ((size_t)b * U_ + u0) * 160);
        #pragma unroll
        for (int i = 0; i < 5; i++) {
            int idx = tid + i * 128;
            int row = idx / 40, q = idx - row * 40;
            uint4 v = src[idx];
            uint32_t* d = sm + OFF_P + row * EPS + (q >> 1) * 8 + (q & 1);
            d[0] = v.x; d[2] = v.y; d[4] = v.z; d[6] = v.w;
        }
    }

    // e fill geometry: 8 rows x 40 uint4 = 320 items, 128 threads
    int frow[3], fq[3];
    bool fon[3];
    #pragma unroll
    for (int i = 0; i < 3; i++) {
        int idx = tid + i * 128;
        fon[i] = idx < 320;
        int idc = fon[i] ? idx : 0;
        frow[i] = idc / 40; fq[i] = idc - frow[i] * 40;
    }

    const uint32_t* eB  = sm + OFF_E + (2 * wid) * EPS + c2;
    const uint32_t* pB0 = sm + OFF_P + rn * EPS + c2;
    const uint32_t* pB1 = pB0 + 8 * EPS;
    const uint32_t* wB  = sm + OFF_W + (c * WG44 + rn) * 2;

    float bn[NT5][2];
    #pragma unroll
    for (int nt = 0; nt < NT5; nt++) {
        bn[nt][0] = (nt * 8 + c2 < C_)     ? b_out[nt * 8 + c2]     : -1e30f;
        bn[nt][1] = (nt * 8 + c2 + 1 < C_) ? b_out[nt * 8 + c2 + 1] : -1e30f;
    }

    for (int pass = 0; pass < 4; pass++) {
        const int t0 = tbase + pass * 8;
        __syncthreads();
        {
            const uint4* src = (const uint4*)(g_e + ((size_t)b * T_ + t0) * 160);
            #pragma unroll
            for (int i = 0; i < 3; i++) {
                if (fon[i]) {
                    uint4 v = src[tid + i * 128];
                    uint32_t* d = sm + OFF_E + frow[i] * EPS
                                + (fq[i] >> 1) * 8 + (fq[i] & 1);
                    d[0] = v.x; d[2] = v.y; d[4] = v.z; d[6] = v.w;
                }
            }
        }
        __syncthreads();

        float acc[2][NT5][4];
        #pragma unroll
        for (int mt = 0; mt < 2; mt++)
            #pragma unroll
            for (int nt = 0; nt < NT5; nt++)
                #pragma unroll
                for (int i = 0; i < 4; i++) acc[mt][nt][i] = 0.f;

        #pragma unroll 4
        for (int g = 0; g < 20; g++) {
            uint2 pv0 = *(const uint2*)(pB0 + 8 * g);
            uint2 pv1 = *(const uint2*)(pB1 + 8 * g);
            uint32_t A[2][4];
            #pragma unroll
            for (int mt = 0; mt < 2; mt++) {
                uint2 ev = *(const uint2*)(eB + mt * EPS + 8 * g);
                A[mt][0] = hrelu2(hadd2u(ev.x, pv0.x));
                A[mt][1] = hrelu2(hadd2u(ev.x, pv1.x));
                A[mt][2] = hrelu2(hadd2u(ev.y, pv0.y));
                A[mt][3] = hrelu2(hadd2u(ev.y, pv1.y));
            }
            #pragma unroll
            for (int nt = 0; nt < NT5; nt++) {
                uint2 wv = *(const uint2*)(wB + g * (4 * WG44 * 2) + nt * 16);
                mma_f16(acc[0][nt], A[0], wv.x, wv.y);
                mma_f16(acc[1][nt], A[1], wv.x, wv.y);
            }
        }

        #pragma unroll
        for (int mt = 0; mt < 2; mt++) {
            const int t = t0 + 2 * wid + mt;
            #pragma unroll
            for (int hf = 0; hf < 2; hf++) {
                float v[NT5][2];
                #pragma unroll
                for (int nt = 0; nt < NT5; nt++) {
                    v[nt][0] = acc[mt][nt][hf * 2 + 0] + bn[nt][0];
                    v[nt][1] = acc[mt][nt][hf * 2 + 1] + bn[nt][1];
                }
                float m = v[0][0];
                #pragma unroll
                for (int nt = 0; nt < NT5; nt++) {
                    m = fmaxf(m, v[nt][0]);
                    m = fmaxf(m, v[nt][1]);
                }
                m = fmaxf(m, __shfl_xor_sync(0xffffffffu, m, 1));
                m = fmaxf(m, __shfl_xor_sync(0xffffffffu, m, 2));
                float s = 0.f;
                #pragma unroll
                for (int nt = 0; nt < NT5; nt++) {
                    s += __expf(v[nt][0] - m);
                    s += __expf(v[nt][1] - m);
                }
                s += __shfl_xor_sync(0xffffffffu, s, 1);
                s += __shfl_xor_sync(0xffffffffu, s, 2);
                float lse = m + __logf(s);

                const int u = u0 + rn + 8 * hf;
                float* o = out + (((size_t)b * T_ + t) * U_ + u) * C_;
                #pragma unroll
                for (int nt = 0; nt < 4; nt++)
                    *(float2*)(o + nt * 8 + c2) =
                        make_float2(v[nt][0] - lse, v[nt][1] - lse);
                if (c == 0)
                    *(float2*)(o + 32) = make_float2(v[4][0] - lse, v[4][1] - lse);
            }
        }
    }
}

// =====================================================================
// kernel_launch
// Inputs: enc, dec, W_enc, b_enc, W_pred, b_pred, W_out, b_out
// =====================================================================
extern "C" void kernel_launch(void* const* d_in, const int* in_sizes, int n_in,
                              void* d_out, int out_size)
{
    const float* enc    = (const float*)d_in[0];
    const float* dec    = (const float*)d_in[1];
    const float* W_enc  = (const float*)d_in[2];
    const float* b_enc  = (const float*)d_in[3];
    const float* W_pred = (const float*)d_in[4];
    const float* b_pred = (const float*)d_in[5];
    const float* W_out  = (const float*)d_in[6];
    const float* b_outp = (const float*)d_in[7];
    float* out = (float*)d_out;

    (void)cudaFuncSetAttribute(joint_mma_kernel,
                               cudaFuncAttributeMaxDynamicSharedMemorySize,
                               SMEM_JT);

    // proj: 640 enc + 160 dec = 800 blocks
    proj_kernel<<<800, 128>>>(enc, W_enc, b_enc, dec, W_pred, b_pred);

    // joint: 8 x 8 x 16 = 1024 blocks, 4 passes each
    joint_mma_kernel<<<dim3(U_ / 16, B_, T_ / 32), 128, SMEM_JT>>>(
        W_out, b_outp, out);
}

// round 17
// speedup vs baseline: 1.2534x; 1.0232x over previous
#include <cuda_runtime.h>
#include <cuda_fp16.h>
#include <cstdint>
#include <cstddef>

typedef unsigned long long ull;

#define B_   8
#define EH_  768
#define T_   512
#define PH_  320
#define U_   128
#define JH_  320
#define C_   34
#define NPAD 40
#define NT5  5

// ---------------- scratch: e/p activations stored as half2 words ----------
__device__ __align__(16) uint32_t g_e[B_ * T_ * JH_ / 2];
__device__ __align__(16) uint32_t g_p[B_ * U_ * JH_ / 2];

// ---------------- helpers ----------------
__device__ __forceinline__ uint32_t pkh(float lo, float hi) {
    uint32_t d;
    asm("cvt.rn.f16x2.f32 %0, %1, %2;" : "=r"(d) : "f"(hi), "f"(lo));
    return d;
}
__device__ __forceinline__ uint32_t hadd2u(uint32_t a, uint32_t b) {
    uint32_t d;
    asm("add.f16x2 %0, %1, %2;" : "=r"(d) : "r"(a), "r"(b));
    return d;
}
__device__ __forceinline__ uint32_t hrelu2(uint32_t a) {
    uint32_t d;
    asm("max.f16x2 %0, %1, %2;" : "=r"(d) : "r"(a), "r"(0u));
    return d;
}
__device__ __forceinline__ void mma_f16(float* d, const uint32_t* a,
                                        uint32_t b0, uint32_t b1) {
    asm volatile(
        "mma.sync.aligned.m16n8k16.row.col.f32.f16.f16.f32 "
        "{%0,%1,%2,%3}, {%4,%5,%6,%7}, {%8,%9}, {%0,%1,%2,%3};"
        : "+f"(d[0]), "+f"(d[1]), "+f"(d[2]), "+f"(d[3])
        : "r"(a[0]), "r"(a[1]), "r"(a[2]), "r"(a[3]), "r"(b0), "r"(b1));
}

// =====================================================================
// proj_kernel (unchanged from R13): fp16 m16n8k16 MMA, D^T = W @ X.
//   Block: 64 j x 32 l, 128 thr, warp = 2 m16(j) x 2 n8(l). 800 blocks.
// =====================================================================
#define PWS 20
#define PXS 40
#define SS_STRW 36

__global__ void __launch_bounds__(128, 6) proj_kernel(
    const float* __restrict__ enc, const float* __restrict__ W_enc,
    const float* __restrict__ b_enc, const float* __restrict__ dec,
    const float* __restrict__ W_pred, const float* __restrict__ b_pred)
{
    __shared__ __align__(16) uint32_t sW[64 * PWS];
    __shared__ __align__(16) uint32_t sXS[32 * SS_STRW];

    const int blk = blockIdx.x;
    const float *X, *W, *bias;
    uint32_t* outw;
    int H, L, b, j0, l0;
    if (blk < 640) {
        b = blk / 80; int r = blk - b * 80;
        j0 = (r >> 4) * 64; l0 = (r & 15) * 32;
        X = enc; W = W_enc; bias = b_enc; outw = g_e; H = EH_; L = T_;
    } else {
        int bi = blk - 640; b = bi / 20; int r = bi - b * 20;
        j0 = (r >> 2) * 64; l0 = (r & 3) * 32;
        X = dec; W = W_pred; bias = b_pred; outw = g_p; H = PH_; L = U_;
    }
    const float* Xb = X + (size_t)b * H * L + l0;
    const float* Wb = W + (size_t)j0 * H;

    const int tid  = threadIdx.x;
    const int wid  = tid >> 5;
    const int lane = tid & 31;
    const int c    = lane & 3;
    const int rn   = lane >> 2;
    const int mpair = wid >> 1;
    const int nhalf = wid & 1;

    float acc[2][2][4];
    #pragma unroll
    for (int mt = 0; mt < 2; mt++)
        #pragma unroll
        for (int nt = 0; nt < 2; nt++)
            #pragma unroll
            for (int i = 0; i < 4; i++) acc[mt][nt][i] = 0.f;

    const int nk = H >> 5;
    for (int kc = 0; kc < nk; kc++) {
        const int k0 = kc * 32;
        {
            int h2 = tid >> 3, l4 = (tid & 7) * 4;
            const float* r0 = Xb + (size_t)(k0 + 2 * h2) * L + l4;
            float4 v0 = *(const float4*)r0;
            float4 v1 = *(const float4*)(r0 + L);
            uint4 u;
            u.x = pkh(v0.x, v1.x);
            u.y = pkh(v0.y, v1.y);
            u.z = pkh(v0.z, v1.z);
            u.w = pkh(v0.w, v1.w);
            *(uint4*)(sXS + h2 * PXS + l4) = u;
        }
        #pragma unroll
        for (int i = 0; i < 4; i++) {
            int idx = tid + i * 128;
            int jj = idx >> 3, h4 = (idx & 7) * 4;
            float4 v = *(const float4*)(Wb + (size_t)jj * H + k0 + h4);
            uint2 u;
            u.x = pkh(v.x, v.y);
            u.y = pkh(v.z, v.w);
            *(uint2*)(sW + jj * PWS + (h4 >> 1)) = u;
        }
        __syncthreads();
        #pragma unroll
        for (int s = 0; s < 2; s++) {
            const int hb = 8 * s;
            uint32_t a0[4], a1[4];
            const uint32_t* w0p = sW + (32 * mpair + rn) * PWS + hb + c;
            a0[0] = w0p[0];
            a0[1] = w0p[8 * PWS];
            a0[2] = w0p[4];
            a0[3] = w0p[8 * PWS + 4];
            const uint32_t* w1p = w0p + 16 * PWS;
            a1[0] = w1p[0];
            a1[1] = w1p[8 * PWS];
            a1[2] = w1p[4];
            a1[3] = w1p[8 * PWS + 4];
            const uint32_t* bp = sXS + (hb + c) * PXS + 16 * nhalf + rn;
            #pragma unroll
            for (int nt = 0; nt < 2; nt++) {
                uint32_t b0 = bp[8 * nt];
                uint32_t b1 = bp[4 * PXS + 8 * nt];
                mma_f16(acc[0][nt], a0, b0, b1);
                mma_f16(acc[1][nt], a1, b0, b1);
            }
        }
        __syncthreads();
    }

    float bj[2][2];
    #pragma unroll
    for (int mt = 0; mt < 2; mt++) {
        int jr = j0 + 16 * (2 * mpair + mt) + rn;
        bj[mt][0] = bias[jr];
        bj[mt][1] = bias[jr + 8];
    }
    __half* sS = (__half*)sXS;
    #pragma unroll
    for (int mt = 0; mt < 2; mt++) {
        int jloc = 16 * (2 * mpair + mt) + rn;
        #pragma unroll
        for (int nt = 0; nt < 2; nt++) {
            int lloc = 8 * (2 * nhalf + nt) + 2 * c;
            sS[lloc * 72 + jloc]           = __float2half(acc[mt][nt][0] + bj[mt][0]);
            sS[(lloc + 1) * 72 + jloc]     = __float2half(acc[mt][nt][1] + bj[mt][0]);
            sS[lloc * 72 + jloc + 8]       = __float2half(acc[mt][nt][2] + bj[mt][1]);
            sS[(lloc + 1) * 72 + jloc + 8] = __float2half(acc[mt][nt][3] + bj[mt][1]);
        }
    }
    __syncthreads();
    #pragma unroll
    for (int i = 0; i < 2; i++) {
        int idx = tid + i * 128;
        int l = idx >> 3, q = idx & 7;
        uint4 v = *(const uint4*)(sXS + l * SS_STRW + q * 4);
        *(uint4*)(outw + ((size_t)b * L + l0 + l) * 160 + (j0 >> 1) + q * 4) = v;
    }
}

// =====================================================================
// joint_mma_kernel: fp16 mma.sync, WARP-DECOUPLED passes.
//   In the pass loop each warp touches only ITS OWN 2 e-rows; p and W
//   are read-only after the preamble. So e-fill is warp-private and the
//   pass loop contains NO block barriers — warps free-run and cover
//   each other's fill/epilogue latencies.
//   Grid 1024 blocks, 4 passes of 8 t-rows x 16 u, 5 blocks/SM.
// =====================================================================
#define EPS   168
#define WG44  44
#define OFF_W 0
#define W_WORDS (20 * 4 * WG44 * 2)     // 7040
#define OFF_E (OFF_W + W_WORDS)         // 7040
#define E_WORDS (8 * EPS)               // 1344
#define OFF_P (OFF_E + E_WORDS)         // 8384
#define P_WORDS (16 * EPS)              // 2688
#define SMEM_JT ((OFF_P + P_WORDS) * 4) // 44288 B

__global__ void __launch_bounds__(128, 5) joint_mma_kernel(
    const float* __restrict__ W_out, const float* __restrict__ b_out,
    float* __restrict__ out)
{
    extern __shared__ __align__(16) uint32_t sm[];

    const int tid  = threadIdx.x;
    const int wid  = tid >> 5;
    const int lane = tid & 31;
    const int c    = lane & 3;
    const int rn   = lane >> 2;
    const int c2   = c * 2;
    const int b    = blockIdx.y;
    const int u0   = blockIdx.x * 16;
    const int tbase = blockIdx.z * 32;

    // ---- W_out -> [g][c][n][pair] half2 layout (div-free) ----
    for (int n = wid; n < NPAD; n += 4) {
        const float2* wrow = (const float2*)(W_out + (size_t)n * JH_);
        #pragma unroll
        for (int k2s = 0; k2s < 160; k2s += 32) {
            int k2 = k2s + lane;
            uint32_t v = 0u;
            if (n < C_) { float2 w = wrow[k2]; v = pkh(w.x, w.y); }
            int g = k2 >> 3, r = k2 & 7;
            sm[OFF_W + ((g * 4 + (r & 3)) * WG44 + n) * 2 + (r >> 2)] = v;
        }
    }

    // ---- p tile (16 u rows), pair-interleaved ----
    {
        const uint4* src = (const uint4*)(g_p + ((size_t)b * U_ + u0) * 160);
        #pragma unroll
        for (int i = 0; i < 5; i++) {
            int idx = tid + i * 128;
            int row = idx / 40, q = idx - row * 40;
            uint4 v = src[idx];
            uint32_t* d = sm + OFF_P + row * EPS + (q >> 1) * 8 + (q & 1);
            d[0] = v.x; d[2] = v.y; d[4] = v.z; d[6] = v.w;
        }
    }
    __syncthreads();   // ONLY block barrier: W + p visible to all warps

    // ---- warp-private e fill geometry: 2 rows x 40 uint4 = 80 items ----
    // lane handles items {lane, lane+32, lane+64(<80)}
    int erow[3], eq[3];
    bool eon[3];
    #pragma unroll
    for (int i = 0; i < 3; i++) {
        int idx = lane + i * 32;
        eon[i] = idx < 80;
        int idc = eon[i] ? idx : 0;
        erow[i] = idc / 40; eq[i] = idc - erow[i] * 40;
    }

    const uint32_t* eB  = sm + OFF_E + (2 * wid) * EPS + c2;
    const uint32_t* pB0 = sm + OFF_P + rn * EPS + c2;
    const uint32_t* pB1 = pB0 + 8 * EPS;
    const uint32_t* wB  = sm + OFF_W + (c * WG44 + rn) * 2;
    uint32_t* eW = sm + OFF_E + (2 * wid) * EPS;   // warp's own region

    float bn[NT5][2];
    #pragma unroll
    for (int nt = 0; nt < NT5; nt++) {
        bn[nt][0] = (nt * 8 + c2 < C_)     ? b_out[nt * 8 + c2]     : -1e30f;
        bn[nt][1] = (nt * 8 + c2 + 1 < C_) ? b_out[nt * 8 + c2 + 1] : -1e30f;
    }

    for (int pass = 0; pass < 4; pass++) {
        const int t0 = tbase + pass * 8;
        // ---- e fill: warp-private (rows t0+2wid, t0+2wid+1) ----
        {
            const uint4* src = (const uint4*)(g_e +
                ((size_t)b * T_ + t0 + 2 * wid) * 160);
            #pragma unroll
            for (int i = 0; i < 3; i++) {
                if (eon[i]) {
                    uint4 v = src[erow[i] * 40 + eq[i]];
                    uint32_t* d = eW + erow[i] * EPS
                                + (eq[i] >> 1) * 8 + (eq[i] & 1);
                    d[0] = v.x; d[2] = v.y; d[4] = v.z; d[6] = v.w;
                }
            }
        }
        __syncwarp();

        float acc[2][NT5][4];
        #pragma unroll
        for (int mt = 0; mt < 2; mt++)
            #pragma unroll
            for (int nt = 0; nt < NT5; nt++)
                #pragma unroll
                for (int i = 0; i < 4; i++) acc[mt][nt][i] = 0.f;

        #pragma unroll 4
        for (int g = 0; g < 20; g++) {
            uint2 pv0 = *(const uint2*)(pB0 + 8 * g);
            uint2 pv1 = *(const uint2*)(pB1 + 8 * g);
            uint32_t A[2][4];
            #pragma unroll
            for (int mt = 0; mt < 2; mt++) {
                uint2 ev = *(const uint2*)(eB + mt * EPS + 8 * g);
                A[mt][0] = hrelu2(hadd2u(ev.x, pv0.x));
                A[mt][1] = hrelu2(hadd2u(ev.x, pv1.x));
                A[mt][2] = hrelu2(hadd2u(ev.y, pv0.y));
                A[mt][3] = hrelu2(hadd2u(ev.y, pv1.y));
            }
            #pragma unroll
            for (int nt = 0; nt < NT5; nt++) {
                uint2 wv = *(const uint2*)(wB + g * (4 * WG44 * 2) + nt * 16);
                mma_f16(acc[0][nt], A[0], wv.x, wv.y);
                mma_f16(acc[1][nt], A[1], wv.x, wv.y);
            }
        }

        // ---- epilogue: bias + log_softmax, direct stores, no barrier ----
        #pragma unroll
        for (int mt = 0; mt < 2; mt++) {
            const int t = t0 + 2 * wid + mt;
            #pragma unroll
            for (int hf = 0; hf < 2; hf++) {
                float v[NT5][2];
                #pragma unroll
                for (int nt = 0; nt < NT5; nt++) {
                    v[nt][0] = acc[mt][nt][hf * 2 + 0] + bn[nt][0];
                    v[nt][1] = acc[mt][nt][hf * 2 + 1] + bn[nt][1];
                }
                float m = v[0][0];
                #pragma unroll
                for (int nt = 0; nt < NT5; nt++) {
                    m = fmaxf(m, v[nt][0]);
                    m = fmaxf(m, v[nt][1]);
                }
                m = fmaxf(m, __shfl_xor_sync(0xffffffffu, m, 1));
                m = fmaxf(m, __shfl_xor_sync(0xffffffffu, m, 2));
                float s = 0.f;
                #pragma unroll
                for (int nt = 0; nt < NT5; nt++) {
                    s += __expf(v[nt][0] - m);
                    s += __expf(v[nt][1] - m);
                }
                s += __shfl_xor_sync(0xffffffffu, s, 1);
                s += __shfl_xor_sync(0xffffffffu, s, 2);
                float lse = m + __logf(s);

                const int u = u0 + rn + 8 * hf;
                float* o = out + (((size_t)b * T_ + t) * U_ + u) * C_;
                #pragma unroll
                for (int nt = 0; nt < 4; nt++)
                    *(float2*)(o + nt * 8 + c2) =
                        make_float2(v[nt][0] - lse, v[nt][1] - lse);
                if (c == 0)
                    *(float2*)(o + 32) = make_float2(v[4][0] - lse, v[4][1] - lse);
            }
        }
        __syncwarp();   // all lanes done reading sE before next fill
    }
}

// =====================================================================
// kernel_launch
// Inputs: enc, dec, W_enc, b_enc, W_pred, b_pred, W_out, b_out
// =====================================================================
extern "C" void kernel_launch(void* const* d_in, const int* in_sizes, int n_in,
                              void* d_out, int out_size)
{
    const float* enc    = (const float*)d_in[0];
    const float* dec    = (const float*)d_in[1];
    const float* W_enc  = (const float*)d_in[2];
    const float* b_enc  = (const float*)d_in[3];
    const float* W_pred = (const float*)d_in[4];
    const float* b_pred = (const float*)d_in[5];
    const float* W_out  = (const float*)d_in[6];
    const float* b_outp = (const float*)d_in[7];
    float* out = (float*)d_out;

    (void)cudaFuncSetAttribute(joint_mma_kernel,
                               cudaFuncAttributeMaxDynamicSharedMemorySize,
                               SMEM_JT);

    // proj: 640 enc + 160 dec = 800 blocks
    proj_kernel<<<800, 128>>>(enc, W_enc, b_enc, dec, W_pred, b_pred);

    // joint: 8 x 8 x 16 = 1024 blocks, 4 warp-decoupled passes each
    joint_mma_kernel<<<dim3(U_ / 16, B_, T_ / 32), 128, SMEM_JT>>>(
        W_out, b_outp, out);
}